// round 3
// baseline (speedup 1.0000x reference)
#include <cuda_runtime.h>
#include <cstdint>

// ---------------------------------------------------------------------------
// DeformableBlock R3: FUSED gather+tf32 GEMM (no im2col buffer).
//   B=4, C=256, H=W=64.
//   x->NHWC; offset conv (c-split partials); precomp bilinear idx/weights;
//   fused GEMM: gather-on-the-fly A tiles + cp.async B, mma.sync tf32;
//   GroupNorm(32)+ReLU epilogue.
// ---------------------------------------------------------------------------

#define BATCH 4
#define CIN   256
#define COUT  256
#define HH    64
#define WW    64
#define HWSZ  (HH*WW)          // 4096
#define NPIX  (BATCH*HWSZ)     // 16384
#define KT    9
#define KDIM  (KT*CIN)         // 2304
#define OCOFF 18
#define GROUPS 32
#define CPG   (COUT/GROUPS)    // 8

__device__ float  g_xt  [NPIX * CIN];          // x NHWC (L2-resident)
__device__ float  g_offp[4][NPIX * OCOFF];     // offset conv partials
__device__ float  g_wt  [KDIM * COUT];         // W^T, tf32-rounded
__device__ int4   g_sidx[NPIX * KT];           // bilinear corner hw-indices
__device__ float4 g_sw  [NPIX * KT];           // bilinear corner weights
__device__ float  g_P   [NPIX * COUT];         // pre-GN result
__device__ float  g_stat[BATCH * GROUPS * 2];  // mean / rstd

__device__ __forceinline__ float to_tf32(float x) {
    float r;
    asm("cvt.rna.tf32.f32 %0, %1;" : "=f"(r) : "f"(x));
    return r;
}
__device__ __forceinline__ unsigned sptr(const void* p) {
    return (unsigned)__cvta_generic_to_shared(p);
}
#define CP_ASYNC16(dst, src) \
    asm volatile("cp.async.cg.shared.global [%0], [%1], 16;\n" :: "r"(dst), "l"(src))
#define CP_COMMIT() asm volatile("cp.async.commit_group;\n")

// ---------------------------------------------------------------------------
// K0: x NCHW -> NHWC
// ---------------------------------------------------------------------------
__global__ void k_transpose_x(const float* __restrict__ x) {
    __shared__ float tile[32][33];
    int b = blockIdx.z, hw0 = blockIdx.x * 32, c0 = blockIdx.y * 32;
    int tx = threadIdx.x, ty = threadIdx.y;
#pragma unroll
    for (int i = 0; i < 4; i++) {
        int c = c0 + ty + i * 8;
        tile[ty + i * 8][tx] = x[((long)b * CIN + c) * HWSZ + hw0 + tx];
    }
    __syncthreads();
#pragma unroll
    for (int i = 0; i < 4; i++) {
        int hw = hw0 + ty + i * 8;
        g_xt[((long)b * HWSZ + hw) * CIN + c0 + tx] = tile[tx][ty + i * 8];
    }
}

// ---------------------------------------------------------------------------
// K0b: deform_w [O][C][3][3] -> g_wt[(k*256+c)*256 + o], tf32-rounded
// ---------------------------------------------------------------------------
__global__ void k_transpose_w(const float* __restrict__ dw) {
    int idx = blockIdx.x * blockDim.x + threadIdx.x;
    if (idx >= KDIM * COUT) return;
    int o = idx & 255;
    int c = (idx >> 8) & 255;
    int k = idx >> 16;
    g_wt[idx] = to_tf32(dw[(o * CIN + c) * KT + k]);
}

// ---------------------------------------------------------------------------
// K1: offset conv 3x3, C-split into 4 chunks of 64 (256 CTAs), partials out.
// ---------------------------------------------------------------------------
__global__ __launch_bounds__(256) void k_offset_conv(const float* __restrict__ ow) {
    int bz    = blockIdx.z;
    int b     = bz >> 2;
    int chunk = bz & 3;
    int x0 = blockIdx.x * 16, y0 = blockIdx.y * 16;
    int tid = threadIdx.x;
    int tx = tid & 15, ty = tid >> 4;

    __shared__ float sx[8][18][18];
    __shared__ float swf[8 * 9 * 20];

    float acc[20];
#pragma unroll
    for (int i = 0; i < 20; i++) acc[i] = 0.f;

    int cbeg = chunk * 64;
    for (int c0 = cbeg; c0 < cbeg + 64; c0 += 8) {
        for (int i = tid; i < 18 * 18 * 8; i += 256) {
            int cc = i & 7, p = i >> 3;
            int xx = p % 18, yy = p / 18;
            int gy = y0 + yy - 1, gx = x0 + xx - 1;
            float v = 0.f;
            if (gy >= 0 && gy < HH && gx >= 0 && gx < WW)
                v = g_xt[((b * HWSZ) + gy * WW + gx) * CIN + c0 + cc];
            sx[cc][yy][xx] = v;
        }
        for (int i = tid; i < 8 * 9 * 20; i += 256) {
            int oc = i % 20, j = (i / 20) % 9, cc = i / 180;
            swf[i] = (oc < OCOFF) ? ow[(oc * CIN + c0 + cc) * KT + j] : 0.f;
        }
        __syncthreads();
#pragma unroll
        for (int cc = 0; cc < 8; cc++) {
            float v[9];
#pragma unroll
            for (int j = 0; j < 9; j++)
                v[j] = sx[cc][ty + j / 3][tx + j % 3];
#pragma unroll
            for (int j = 0; j < 9; j++) {
                const float4* wp = reinterpret_cast<const float4*>(&swf[(cc * 9 + j) * 20]);
#pragma unroll
                for (int q = 0; q < 5; q++) {
                    float4 w = wp[q];
                    acc[q * 4 + 0] += v[j] * w.x;
                    acc[q * 4 + 1] += v[j] * w.y;
                    acc[q * 4 + 2] += v[j] * w.z;
                    acc[q * 4 + 3] += v[j] * w.w;
                }
            }
        }
        __syncthreads();
    }
    int pix = b * HWSZ + (y0 + ty) * WW + (x0 + tx);
#pragma unroll
    for (int oc = 0; oc < OCOFF; oc++)
        g_offp[chunk][pix * OCOFF + oc] = acc[oc];
}

// ---------------------------------------------------------------------------
// K2: precompute bilinear corner indices + weights per (pixel, tap).
//     Also folds the partial-sum combine + bias of the offset conv.
// ---------------------------------------------------------------------------
__global__ void k_precomp(const float* __restrict__ ob) {
    int i = blockIdx.x * 256 + threadIdx.x;
    if (i >= NPIX * KT) return;
    int tp = i % 9, pix = i / 9;
    float dy = ob[2 * tp], dx = ob[2 * tp + 1];
#pragma unroll
    for (int ch = 0; ch < 4; ch++) {
        dy += g_offp[ch][pix * OCOFF + 2 * tp];
        dx += g_offp[ch][pix * OCOFF + 2 * tp + 1];
    }
    int h = (pix >> 6) & 63, w = pix & 63;
    int ky = tp / 3, kx = tp % 3;
    float py = (float)(h - 1 + ky) + dy;
    float px = (float)(w - 1 + kx) + dx;
    float y0f = floorf(py), x0f = floorf(px);
    float ty = py - y0f, tx = px - x0f;
    int y0 = (int)y0f, x0 = (int)x0f;
    int y1 = y0 + 1, x1 = x0 + 1;
    float vy0 = (y0 >= 0 && y0 < HH) ? 1.f : 0.f;
    float vy1 = (y1 >= 0 && y1 < HH) ? 1.f : 0.f;
    float vx0 = (x0 >= 0 && x0 < WW) ? 1.f : 0.f;
    float vx1 = (x1 >= 0 && x1 < WW) ? 1.f : 0.f;
    int yc0 = min(max(y0, 0), HH - 1), yc1 = min(max(y1, 0), HH - 1);
    int xc0 = min(max(x0, 0), WW - 1), xc1 = min(max(x1, 0), WW - 1);
    g_sidx[i] = make_int4(yc0 * WW + xc0, yc0 * WW + xc1,
                          yc1 * WW + xc0, yc1 * WW + xc1);
    g_sw[i] = make_float4((1.f - ty) * (1.f - tx) * vy0 * vx0,
                          (1.f - ty) * tx * vy0 * vx1,
                          ty * (1.f - tx) * vy1 * vx0,
                          ty * tx * vy1 * vx1);
}

// ---------------------------------------------------------------------------
// K3: FUSED gather + tf32 GEMM.
//     grid = 128 (M blocks of 128 pixels), 512 threads (16 warps, 4x4 grid).
//     Tile: 128 x 256(all N) x BK=8.  288 chunks = 9 taps x 32 sub-chunks.
//     A tile gathered on the fly from g_xt via precomputed idx/weights;
//     B tile double-buffered via cp.async.
// ---------------------------------------------------------------------------
__global__ __launch_bounds__(512, 1) void k_fused_gemm() {
    __shared__ float As[2][128][12];    // [buf][row][k]  (pad 8->12)
    __shared__ float Bs[2][8][264];     // [buf][k][n]    (pad 256->264)

    int m0 = blockIdx.x * 128;
    int b  = m0 >> 12;                  // batch (blocks don't straddle)
    const float* xb = &g_xt[(long)b * HWSZ * CIN];

    int t = threadIdx.x;
    int row = t >> 2, seg = t & 3;      // gather: 1 row, 2 channels (float2)
    int cseg = seg * 2;
    int pixg = m0 + row;
    int brow = t >> 6, bcol = (t & 63) * 4;  // B cp.async: 1 float4

    int wid = t >> 5, lane = t & 31;
    int wm = wid >> 2, wn = wid & 3;    // 4x4 warps: 32-row x 64-col tiles
    int gp = lane >> 2, tg = lane & 3;

    float acc[2][8][4];
#pragma unroll
    for (int i = 0; i < 2; i++)
#pragma unroll
        for (int j = 0; j < 8; j++)
#pragma unroll
            for (int r = 0; r < 4; r++) acc[i][j][r] = 0.f;

    // bilinear descriptor for current tap (held in regs for 32 chunks)
    int4   I  = g_sidx[pixg * 9];
    float4 Wq = g_sw[pixg * 9];

    float2 gv0, gv1, gv2, gv3;          // staged gather (chunk c+1)
#define GATHER(c0)                                                   \
    do {                                                             \
        gv0 = *(const float2*)&xb[(long)I.x * CIN + (c0) + cseg];    \
        gv1 = *(const float2*)&xb[(long)I.y * CIN + (c0) + cseg];    \
        gv2 = *(const float2*)&xb[(long)I.z * CIN + (c0) + cseg];    \
        gv3 = *(const float2*)&xb[(long)I.w * CIN + (c0) + cseg];    \
    } while (0)

    GATHER(0);
    CP_ASYNC16(sptr(&Bs[0][brow][bcol]), &g_wt[brow * COUT + bcol]);
    CP_COMMIT();

    const int NCHUNK = KDIM / 8;        // 288
    for (int c = 0; c < NCHUNK; c++) {
        int buf = c & 1;

        // combine staged gather -> tf32, deposit into As[buf]
        float2 s;
        s.x = to_tf32(Wq.x * gv0.x + Wq.y * gv1.x + Wq.z * gv2.x + Wq.w * gv3.x);
        s.y = to_tf32(Wq.x * gv0.y + Wq.y * gv1.y + Wq.z * gv2.y + Wq.w * gv3.y);
        asm volatile("cp.async.wait_group 0;\n" ::: "memory");
        *(float2*)&As[buf][row][cseg] = s;
        __syncthreads();

        // prefetch chunk c+1 (gather LDGs + B cp.async) — hides under MMA
        if (c + 1 < NCHUNK) {
            int cn = c + 1;
            int tap = cn >> 5;
            if ((cn & 31) == 0) {
                I  = g_sidx[pixg * 9 + tap];
                Wq = g_sw[pixg * 9 + tap];
            }
            int c0n = (cn & 31) * 8;
            GATHER(c0n);
            CP_ASYNC16(sptr(&Bs[buf ^ 1][brow][bcol]),
                       &g_wt[(cn * 8 + brow) * COUT + bcol]);
            CP_COMMIT();
        }

        // MMA: 2 m-tiles x 8 n-tiles of m16n8k8
#pragma unroll
        for (int mt = 0; mt < 2; mt++) {
            int r = wm * 32 + mt * 16 + gp;
            uint32_t a0 = __float_as_uint(As[buf][r][tg]);
            uint32_t a1 = __float_as_uint(As[buf][r + 8][tg]);
            uint32_t a2 = __float_as_uint(As[buf][r][tg + 4]);
            uint32_t a3 = __float_as_uint(As[buf][r + 8][tg + 4]);
#pragma unroll
            for (int nt = 0; nt < 8; nt++) {
                int ncol = wn * 64 + nt * 8 + gp;
                uint32_t b0 = __float_as_uint(Bs[buf][tg][ncol]);
                uint32_t b1 = __float_as_uint(Bs[buf][tg + 4][ncol]);
                asm volatile(
                    "mma.sync.aligned.m16n8k8.row.col.f32.tf32.tf32.f32 "
                    "{%0,%1,%2,%3}, {%4,%5,%6,%7}, {%8,%9}, {%0,%1,%2,%3};\n"
                    : "+f"(acc[mt][nt][0]), "+f"(acc[mt][nt][1]),
                      "+f"(acc[mt][nt][2]), "+f"(acc[mt][nt][3])
                    : "r"(a0), "r"(a1), "r"(a2), "r"(a3), "r"(b0), "r"(b1));
            }
        }
        __syncthreads();
    }
#undef GATHER

    // epilogue: write P
#pragma unroll
    for (int mt = 0; mt < 2; mt++) {
        int r = m0 + wm * 32 + mt * 16 + gp;
#pragma unroll
        for (int nt = 0; nt < 8; nt++) {
            int nc = wn * 64 + nt * 8 + tg * 2;
            *(float2*)&g_P[(long)r * COUT + nc] =
                make_float2(acc[mt][nt][0], acc[mt][nt][1]);
            *(float2*)&g_P[(long)(r + 8) * COUT + nc] =
                make_float2(acc[mt][nt][2], acc[mt][nt][3]);
        }
    }
}

// ---------------------------------------------------------------------------
// K4: GroupNorm stats
// ---------------------------------------------------------------------------
__global__ __launch_bounds__(256) void k_gn_stats() {
    int b = blockIdx.x >> 5;
    int g = blockIdx.x & 31;
    int tid = threadIdx.x;
    float s = 0.f, ss = 0.f;
    for (int i = tid; i < HWSZ; i += 256) {
        const float* p = &g_P[(long)(b * HWSZ + i) * COUT + g * CPG];
        float4 u = *(const float4*)p;
        float4 v = *(const float4*)(p + 4);
        s  += u.x + u.y + u.z + u.w + v.x + v.y + v.z + v.w;
        ss += u.x * u.x + u.y * u.y + u.z * u.z + u.w * u.w
            + v.x * v.x + v.y * v.y + v.z * v.z + v.w * v.w;
    }
    __shared__ float rs[256], rss[256];
    rs[tid] = s; rss[tid] = ss;
    __syncthreads();
    for (int st = 128; st > 0; st >>= 1) {
        if (tid < st) { rs[tid] += rs[tid + st]; rss[tid] += rss[tid + st]; }
        __syncthreads();
    }
    if (tid == 0) {
        float inv = 1.f / (float)(CPG * HWSZ);
        float mean = rs[0] * inv;
        float var  = rss[0] * inv - mean * mean;
        g_stat[blockIdx.x * 2]     = mean;
        g_stat[blockIdx.x * 2 + 1] = rsqrtf(var + 1e-5f);
    }
}

// ---------------------------------------------------------------------------
// K5: normalize + affine + ReLU + NHWC->NCHW into d_out
// ---------------------------------------------------------------------------
__global__ void k_gn_finalize(float* __restrict__ out,
                              const float* __restrict__ gamma,
                              const float* __restrict__ beta) {
    __shared__ float tile[32][33];
    int b = blockIdx.z, hw0 = blockIdx.x * 32, o0 = blockIdx.y * 32;
    int tx = threadIdx.x, ty = threadIdx.y;

    int o = o0 + tx;
    int g = o >> 3;
    float mean = g_stat[(b * GROUPS + g) * 2];
    float rstd = g_stat[(b * GROUPS + g) * 2 + 1];
    float ga = gamma[o], be = beta[o];

#pragma unroll
    for (int i = 0; i < 4; i++) {
        int hw = hw0 + ty + i * 8;
        float v = g_P[(long)(b * HWSZ + hw) * COUT + o];
        v = (v - mean) * rstd * ga + be;
        tile[ty + i * 8][tx] = fmaxf(v, 0.f);
    }
    __syncthreads();
#pragma unroll
    for (int i = 0; i < 4; i++) {
        int oo = o0 + ty + i * 8;
        out[((long)b * COUT + oo) * HWSZ + hw0 + tx] = tile[tx][ty + i * 8];
    }
}

// ---------------------------------------------------------------------------
extern "C" void kernel_launch(void* const* d_in, const int* in_sizes, int n_in,
                              void* d_out, int out_size) {
    const float* x  = (const float*)d_in[0];
    const float* ow = (const float*)d_in[1];
    const float* ob = (const float*)d_in[2];
    const float* dw = (const float*)d_in[3];
    const float* ga = (const float*)d_in[4];
    const float* be = (const float*)d_in[5];
    float* out = (float*)d_out;

    k_transpose_x<<<dim3(HWSZ / 32, CIN / 32, BATCH), dim3(32, 8)>>>(x);
    k_transpose_w<<<(KDIM * COUT + 255) / 256, 256>>>(dw);
    k_offset_conv<<<dim3(WW / 16, HH / 16, BATCH * 4), 256>>>(ow);
    k_precomp<<<(NPIX * KT + 255) / 256, 256>>>(ob);
    k_fused_gemm<<<NPIX / 128, 512>>>();
    k_gn_stats<<<BATCH * GROUPS, 256>>>();
    k_gn_finalize<<<dim3(HWSZ / 32, COUT / 32, BATCH), dim3(32, 8)>>>(out, ga, be);
}

// round 5
// speedup vs baseline: 1.5193x; 1.5193x over previous
#include <cuda_runtime.h>
#include <cuda_fp16.h>
#include <cstdint>

// ---------------------------------------------------------------------------
// DeformableBlock R5: fp16 mma.m16n8k16 GEMM (compute_103-safe), fp16 gather.
//   x->NHWC (fp32 + fp16 copies); offset conv fp32 (c-split); precomp bilinear;
//   sampler -> fp16 im2col A; GEMM 128x256 tile, BK=32, 3-stage cp.async,
//   ldmatrix fragments; GroupNorm(32)+ReLU epilogue.
// ---------------------------------------------------------------------------

#define BATCH 4
#define CIN   256
#define COUT  256
#define HH    64
#define WW    64
#define HWSZ  4096
#define NPIX  16384
#define KT    9
#define KDIM  2304
#define OCOFF 18
#define GROUPS 32
#define CPG   8
#define NKB   72            // K chunks of 32

__device__ __align__(16) float  g_xt [NPIX * CIN];      // x NHWC fp32
__device__ __align__(16) __half g_xh [NPIX * CIN];      // x NHWC fp16
__device__ float  g_offp[4][NPIX * OCOFF];
__device__ __align__(16) __half g_wtB[NKB * 256 * 32];  // B tiles [kb][o][ko]
__device__ int4   g_sidx[NPIX * KT];
__device__ float4 g_sw  [NPIX * KT];
__device__ __align__(16) __half g_Ah [(size_t)NPIX * KDIM];  // fp16 im2col
__device__ float  g_P   [NPIX * COUT];
__device__ float  g_stat[BATCH * GROUPS * 2];

static __device__ __forceinline__ uint32_t sptr(const void* p) {
    return (uint32_t)__cvta_generic_to_shared(p);
}
#define CP_ASYNC16(dst, src) \
    asm volatile("cp.async.cg.shared.global [%0], [%1], 16;\n" :: "r"(dst), "l"(src))
#define CP_COMMIT() asm volatile("cp.async.commit_group;\n")

#define LDMX4(r0, r1, r2, r3, addr)                                         \
    asm volatile("ldmatrix.sync.aligned.m8n8.x4.shared.b16 {%0,%1,%2,%3}, [%4];" \
                 : "=r"(r0), "=r"(r1), "=r"(r2), "=r"(r3) : "r"(addr))

#define MMA16816(d, a, b)                                                   \
    asm volatile(                                                           \
        "mma.sync.aligned.m16n8k16.row.col.f32.f16.f16.f32 "                \
        "{%0,%1,%2,%3}, {%4,%5,%6,%7}, {%8,%9}, {%0,%1,%2,%3};\n"           \
        : "+f"((d)[0]), "+f"((d)[1]), "+f"((d)[2]), "+f"((d)[3])            \
        : "r"((a)[0]), "r"((a)[1]), "r"((a)[2]), "r"((a)[3]),               \
          "r"((b)[0]), "r"((b)[1]))

// ---------------------------------------------------------------------------
// K0: x NCHW -> NHWC (fp32 + fp16)
// ---------------------------------------------------------------------------
__global__ void k_transpose_x(const float* __restrict__ x) {
    __shared__ float tile[32][33];
    int b = blockIdx.z, hw0 = blockIdx.x * 32, c0 = blockIdx.y * 32;
    int tx = threadIdx.x, ty = threadIdx.y;
#pragma unroll
    for (int i = 0; i < 4; i++) {
        int c = c0 + ty + i * 8;
        tile[ty + i * 8][tx] = x[((long)b * CIN + c) * HWSZ + hw0 + tx];
    }
    __syncthreads();
#pragma unroll
    for (int i = 0; i < 4; i++) {
        int hw = hw0 + ty + i * 8;
        float v = tile[tx][ty + i * 8];
        long idx = ((long)b * HWSZ + hw) * CIN + c0 + tx;
        g_xt[idx] = v;
        g_xh[idx] = __float2half_rn(v);
    }
}

// ---------------------------------------------------------------------------
// K0b: deform_w -> fp16 B tiles  g_wtB[kb][o][ko], k = tap*256 + c
// ---------------------------------------------------------------------------
__global__ void k_prep_w(const float* __restrict__ dw) {
    int idx = blockIdx.x * 256 + threadIdx.x;
    if (idx >= NKB * 8192) return;
    int kb = idx >> 13;
    int rem = idx & 8191;
    int o = rem >> 5, ko = rem & 31;
    int tap = kb >> 3;
    int c = (kb & 7) * 32 + ko;
    g_wtB[idx] = __float2half_rn(dw[(o * CIN + c) * KT + tap]);
}

// ---------------------------------------------------------------------------
// K1: offset conv 3x3, fp32, C-split x4 (256 CTAs), partials out.
// ---------------------------------------------------------------------------
__global__ __launch_bounds__(256) void k_offset_conv(const float* __restrict__ ow) {
    int bz    = blockIdx.z;
    int b     = bz >> 2;
    int chunk = bz & 3;
    int x0 = blockIdx.x * 16, y0 = blockIdx.y * 16;
    int tid = threadIdx.x;
    int tx = tid & 15, ty = tid >> 4;

    __shared__ float sx[8][18][18];
    __shared__ float swf[8 * 9 * 20];

    float acc[20];
#pragma unroll
    for (int i = 0; i < 20; i++) acc[i] = 0.f;

    int cbeg = chunk * 64;
    for (int c0 = cbeg; c0 < cbeg + 64; c0 += 8) {
        for (int i = tid; i < 18 * 18 * 8; i += 256) {
            int cc = i & 7, p = i >> 3;
            int xx = p % 18, yy = p / 18;
            int gy = y0 + yy - 1, gx = x0 + xx - 1;
            float v = 0.f;
            if (gy >= 0 && gy < HH && gx >= 0 && gx < WW)
                v = g_xt[((b * HWSZ) + gy * WW + gx) * CIN + c0 + cc];
            sx[cc][yy][xx] = v;
        }
        for (int i = tid; i < 8 * 9 * 20; i += 256) {
            int oc = i % 20, j = (i / 20) % 9, cc = i / 180;
            swf[i] = (oc < OCOFF) ? ow[(oc * CIN + c0 + cc) * KT + j] : 0.f;
        }
        __syncthreads();
#pragma unroll
        for (int cc = 0; cc < 8; cc++) {
            float v[9];
#pragma unroll
            for (int j = 0; j < 9; j++)
                v[j] = sx[cc][ty + j / 3][tx + j % 3];
#pragma unroll
            for (int j = 0; j < 9; j++) {
                const float4* wp = reinterpret_cast<const float4*>(&swf[(cc * 9 + j) * 20]);
#pragma unroll
                for (int q = 0; q < 5; q++) {
                    float4 w = wp[q];
                    acc[q * 4 + 0] += v[j] * w.x;
                    acc[q * 4 + 1] += v[j] * w.y;
                    acc[q * 4 + 2] += v[j] * w.z;
                    acc[q * 4 + 3] += v[j] * w.w;
                }
            }
        }
        __syncthreads();
    }
    int pix = b * HWSZ + (y0 + ty) * WW + (x0 + tx);
#pragma unroll
    for (int oc = 0; oc < OCOFF; oc++)
        g_offp[chunk][pix * OCOFF + oc] = acc[oc];
}

// ---------------------------------------------------------------------------
// K2: precompute bilinear corner indices + weights (combine partials + bias)
// ---------------------------------------------------------------------------
__global__ void k_precomp(const float* __restrict__ ob) {
    int i = blockIdx.x * 256 + threadIdx.x;
    if (i >= NPIX * KT) return;
    int tp = i % 9, pix = i / 9;
    float dy = ob[2 * tp], dx = ob[2 * tp + 1];
#pragma unroll
    for (int ch = 0; ch < 4; ch++) {
        dy += g_offp[ch][pix * OCOFF + 2 * tp];
        dx += g_offp[ch][pix * OCOFF + 2 * tp + 1];
    }
    int h = (pix >> 6) & 63, w = pix & 63;
    int ky = tp / 3, kx = tp % 3;
    float py = (float)(h - 1 + ky) + dy;
    float px = (float)(w - 1 + kx) + dx;
    float y0f = floorf(py), x0f = floorf(px);
    float ty = py - y0f, tx = px - x0f;
    int y0 = (int)y0f, x0 = (int)x0f;
    int y1 = y0 + 1, x1 = x0 + 1;
    float vy0 = (y0 >= 0 && y0 < HH) ? 1.f : 0.f;
    float vy1 = (y1 >= 0 && y1 < HH) ? 1.f : 0.f;
    float vx0 = (x0 >= 0 && x0 < WW) ? 1.f : 0.f;
    float vx1 = (x1 >= 0 && x1 < WW) ? 1.f : 0.f;
    int yc0 = min(max(y0, 0), HH - 1), yc1 = min(max(y1, 0), HH - 1);
    int xc0 = min(max(x0, 0), WW - 1), xc1 = min(max(x1, 0), WW - 1);
    g_sidx[i] = make_int4(yc0 * WW + xc0, yc0 * WW + xc1,
                          yc1 * WW + xc0, yc1 * WW + xc1);
    g_sw[i] = make_float4((1.f - ty) * (1.f - tx) * vy0 * vx0,
                          (1.f - ty) * tx * vy0 * vx1,
                          ty * (1.f - tx) * vy1 * vx0,
                          ty * tx * vy1 * vx1);
}

// ---------------------------------------------------------------------------
// K3: bilinear im2col -> fp16 A.  One block per (b,h,tap); 128 thr x half2.
// ---------------------------------------------------------------------------
__global__ __launch_bounds__(128) void k_sample() {
    int bk = blockIdx.x;
    int k  = bk % 9;
    int h  = (bk / 9) & 63;
    int b  = bk / (9 * 64);

    __shared__ int   sI[4][64];
    __shared__ float sWt[4][64];
    int tid = threadIdx.x;

    if (tid < 64) {
        int w = tid;
        int i = (b * HWSZ + h * WW + w) * 9 + k;
        int4 I = g_sidx[i];
        float4 Wq = g_sw[i];
        sI[0][w] = I.x; sI[1][w] = I.y; sI[2][w] = I.z; sI[3][w] = I.w;
        sWt[0][w] = Wq.x; sWt[1][w] = Wq.y; sWt[2][w] = Wq.z; sWt[3][w] = Wq.w;
    }
    __syncthreads();

    const __half2* xb = reinterpret_cast<const __half2*>(g_xh + (size_t)b * HWSZ * CIN);
    __half2* Arow = reinterpret_cast<__half2*>(
        g_Ah + (size_t)(b * HWSZ + h * WW) * KDIM + k * CIN) + tid;
#pragma unroll 2
    for (int w = 0; w < 64; w++) {
        float2 v0 = __half22float2(xb[sI[0][w] * 128 + tid]);
        float2 v1 = __half22float2(xb[sI[1][w] * 128 + tid]);
        float2 v2 = __half22float2(xb[sI[2][w] * 128 + tid]);
        float2 v3 = __half22float2(xb[sI[3][w] * 128 + tid]);
        float w0 = sWt[0][w], w1 = sWt[1][w], w2 = sWt[2][w], w3 = sWt[3][w];
        float2 s;
        s.x = w0 * v0.x + w1 * v1.x + w2 * v2.x + w3 * v3.x;
        s.y = w0 * v0.y + w1 * v1.y + w2 * v2.y + w3 * v3.y;
        Arow[(size_t)w * (KDIM / 2)] = __float22half2_rn(s);
    }
}

// ---------------------------------------------------------------------------
// K4: fp16 GEMM  P[16384x256] = A[16384x2304] @ B^T (B[n][k] tiles)
//   grid=128, 512 thr (16 warps: wm=wid&3 -> 32 rows, wn=wid>>2 -> 64 cols)
//   BK=32, 3-stage cp.async pipeline, ldmatrix frags, padded 80B rows.
// ---------------------------------------------------------------------------
#define ASTRIDE 40                      // halfs per A row (32 + 8 pad)
#define A_OFF(s)  ((s) * 10240)         // 128*40*2 bytes
#define B_OFF(s)  (30720 + (s) * 20480) // 256*40*2 bytes
#define GEMM_SMEM (30720 + 3 * 20480)   // 92160

__global__ __launch_bounds__(512, 1) void k_gemm16() {
    extern __shared__ __align__(16) char smem[];
    uint32_t sb = sptr(smem);

    int m0 = blockIdx.x * 128;
    int t = threadIdx.x, lane = t & 31, wid = t >> 5;
    int wm = wid & 3, wn = wid >> 2;

    // load assignments
    int arow = t >> 2, acol = (t & 3) * 8;        // A: 16B per thread
    int brow = t >> 1, bcol = (t & 1) * 16;       // B: 2 x 16B per thread

    float acc[2][8][4];
#pragma unroll
    for (int i = 0; i < 2; i++)
#pragma unroll
        for (int j = 0; j < 8; j++)
#pragma unroll
            for (int r = 0; r < 4; r++) acc[i][j][r] = 0.f;

#define LOAD_CHUNK(st, kb)                                                        \
    do {                                                                          \
        CP_ASYNC16(sb + A_OFF(st) + (arow * ASTRIDE + acol) * 2,                  \
                   g_Ah + (size_t)(m0 + arow) * KDIM + (kb) * 32 + acol);         \
        CP_ASYNC16(sb + B_OFF(st) + (brow * ASTRIDE + bcol) * 2,                  \
                   g_wtB + (kb) * 8192 + brow * 32 + bcol);                       \
        CP_ASYNC16(sb + B_OFF(st) + (brow * ASTRIDE + bcol + 8) * 2,              \
                   g_wtB + (kb) * 8192 + brow * 32 + bcol + 8);                   \
        CP_COMMIT();                                                              \
    } while (0)

    LOAD_CHUNK(0, 0);
    LOAD_CHUNK(1, 1);

    int lrow = lane & 15, lcol = (lane >> 4) * 8;

    for (int c = 0; c < NKB; c++) {
        int st = c % 3;
        if (c + 2 < NKB) {
            LOAD_CHUNK((c + 2) % 3, c + 2);
            asm volatile("cp.async.wait_group 2;" ::: "memory");
        } else if (c + 1 < NKB) {
            asm volatile("cp.async.wait_group 1;" ::: "memory");
        } else {
            asm volatile("cp.async.wait_group 0;" ::: "memory");
        }
        __syncthreads();

        uint32_t Ab = sb + A_OFF(st);
        uint32_t Bb = sb + B_OFF(st);
#pragma unroll
        for (int ks = 0; ks < 32; ks += 16) {
            int col = ks + lcol;
            uint32_t A0[4], A1[4], Bf[8][2], t0, t1, t2, t3;
            LDMX4(A0[0], A0[1], A0[2], A0[3],
                  Ab + ((wm * 32 + lrow) * ASTRIDE + col) * 2);
            LDMX4(A1[0], A1[1], A1[2], A1[3],
                  Ab + ((wm * 32 + 16 + lrow) * ASTRIDE + col) * 2);
#pragma unroll
            for (int np = 0; np < 4; np++) {
                LDMX4(t0, t1, t2, t3,
                      Bb + ((wn * 64 + np * 16 + lrow) * ASTRIDE + col) * 2);
                Bf[np * 2][0] = t0;  Bf[np * 2][1] = t2;
                Bf[np * 2 + 1][0] = t1;  Bf[np * 2 + 1][1] = t3;
            }
#pragma unroll
            for (int nt = 0; nt < 8; nt++) {
                MMA16816(acc[0][nt], A0, Bf[nt]);
                MMA16816(acc[1][nt], A1, Bf[nt]);
            }
        }
        __syncthreads();
    }
#undef LOAD_CHUNK

    // epilogue
#pragma unroll
    for (int mt = 0; mt < 2; mt++) {
        int row = m0 + wm * 32 + mt * 16 + (lane >> 2);
#pragma unroll
        for (int nt = 0; nt < 8; nt++) {
            int col = wn * 64 + nt * 8 + (lane & 3) * 2;
            *(float2*)&g_P[(size_t)row * COUT + col] =
                make_float2(acc[mt][nt][0], acc[mt][nt][1]);
            *(float2*)&g_P[(size_t)(row + 8) * COUT + col] =
                make_float2(acc[mt][nt][2], acc[mt][nt][3]);
        }
    }
}

// ---------------------------------------------------------------------------
// K5: GroupNorm stats
// ---------------------------------------------------------------------------
__global__ __launch_bounds__(256) void k_gn_stats() {
    int b = blockIdx.x >> 5;
    int g = blockIdx.x & 31;
    int tid = threadIdx.x;
    float s = 0.f, ss = 0.f;
    for (int i = tid; i < HWSZ; i += 256) {
        const float* p = &g_P[(long)(b * HWSZ + i) * COUT + g * CPG];
        float4 u = *(const float4*)p;
        float4 v = *(const float4*)(p + 4);
        s  += u.x + u.y + u.z + u.w + v.x + v.y + v.z + v.w;
        ss += u.x * u.x + u.y * u.y + u.z * u.z + u.w * u.w
            + v.x * v.x + v.y * v.y + v.z * v.z + v.w * v.w;
    }
    __shared__ float rs[256], rss[256];
    rs[tid] = s; rss[tid] = ss;
    __syncthreads();
    for (int st = 128; st > 0; st >>= 1) {
        if (tid < st) { rs[tid] += rs[tid + st]; rss[tid] += rss[tid + st]; }
        __syncthreads();
    }
    if (tid == 0) {
        float inv = 1.f / (float)(CPG * HWSZ);
        float mean = rs[0] * inv;
        float var  = rss[0] * inv - mean * mean;
        g_stat[blockIdx.x * 2]     = mean;
        g_stat[blockIdx.x * 2 + 1] = rsqrtf(var + 1e-5f);
    }
}

// ---------------------------------------------------------------------------
// K6: normalize + affine + ReLU + NHWC->NCHW into d_out
// ---------------------------------------------------------------------------
__global__ void k_gn_finalize(float* __restrict__ out,
                              const float* __restrict__ gamma,
                              const float* __restrict__ beta) {
    __shared__ float tile[32][33];
    int b = blockIdx.z, hw0 = blockIdx.x * 32, o0 = blockIdx.y * 32;
    int tx = threadIdx.x, ty = threadIdx.y;

    int o = o0 + tx;
    int g = o >> 3;
    float mean = g_stat[(b * GROUPS + g) * 2];
    float rstd = g_stat[(b * GROUPS + g) * 2 + 1];
    float ga = gamma[o], be = beta[o];

#pragma unroll
    for (int i = 0; i < 4; i++) {
        int hw = hw0 + ty + i * 8;
        float v = g_P[(long)(b * HWSZ + hw) * COUT + o];
        v = (v - mean) * rstd * ga + be;
        tile[ty + i * 8][tx] = fmaxf(v, 0.f);
    }
    __syncthreads();
#pragma unroll
    for (int i = 0; i < 4; i++) {
        int oo = o0 + ty + i * 8;
        out[((long)b * COUT + oo) * HWSZ + hw0 + tx] = tile[tx][ty + i * 8];
    }
}

// ---------------------------------------------------------------------------
extern "C" void kernel_launch(void* const* d_in, const int* in_sizes, int n_in,
                              void* d_out, int out_size) {
    const float* x  = (const float*)d_in[0];
    const float* ow = (const float*)d_in[1];
    const float* ob = (const float*)d_in[2];
    const float* dw = (const float*)d_in[3];
    const float* ga = (const float*)d_in[4];
    const float* be = (const float*)d_in[5];
    float* out = (float*)d_out;

    cudaFuncSetAttribute(k_gemm16, cudaFuncAttributeMaxDynamicSharedMemorySize,
                         GEMM_SMEM);

    k_transpose_x<<<dim3(HWSZ / 32, CIN / 32, BATCH), dim3(32, 8)>>>(x);
    k_prep_w<<<(NKB * 8192 + 255) / 256, 256>>>(dw);
    k_offset_conv<<<dim3(WW / 16, HH / 16, BATCH * 4), 256>>>(ow);
    k_precomp<<<(NPIX * KT + 255) / 256, 256>>>(ob);
    k_sample<<<BATCH * HH * KT, 128>>>();
    k_gemm16<<<NPIX / 128, 512, GEMM_SMEM>>>();
    k_gn_stats<<<BATCH * GROUPS, 256>>>();
    k_gn_finalize<<<dim3(HWSZ / 32, COUT / 32, BATCH), dim3(32, 8)>>>(out, ga, be);
}

// round 6
// speedup vs baseline: 1.7771x; 1.1697x over previous
#include <cuda_runtime.h>
#include <cuda_fp16.h>
#include <cstdint>

// ---------------------------------------------------------------------------
// DeformableBlock R6: fp16 mma GEMM with FUSED bilinear gather + GN partials.
//   x->NHWC (fp32+fp16); offset conv fp32 (c-split); precomp bilinear idx/w;
//   k_gemm_fused: gather A on-the-fly (fp32 math -> fp16), 3-stage pipeline,
//                 m16n8k16 MMAs, GN partial sums in epilogue;
//   k_stats_combine + k_gn_finalize.
// ---------------------------------------------------------------------------

#define BATCH 4
#define CIN   256
#define COUT  256
#define HH    64
#define WW    64
#define HWSZ  4096
#define NPIX  16384
#define KT    9
#define KDIM  2304
#define OCOFF 18
#define GROUPS 32
#define CPG   8
#define NKB   72            // K chunks of 32

__device__ __align__(16) float  g_xt [NPIX * CIN];      // x NHWC fp32
__device__ __align__(16) __half g_xh [NPIX * CIN];      // x NHWC fp16
__device__ float  g_offp[4][NPIX * OCOFF];
__device__ __align__(16) __half g_wtB[NKB * 256 * 32];  // B tiles [kb][o][ko]
__device__ int4   g_sidx[NPIX * KT];
__device__ float4 g_sw  [NPIX * KT];
__device__ float  g_P   [NPIX * COUT];
__device__ float2 g_gnp [128 * GROUPS];                 // per-block GN partials
__device__ float  g_stat[BATCH * GROUPS * 2];

static __device__ __forceinline__ uint32_t sptr(const void* p) {
    return (uint32_t)__cvta_generic_to_shared(p);
}
#define CP_ASYNC16(dst, src) \
    asm volatile("cp.async.cg.shared.global [%0], [%1], 16;\n" :: "r"(dst), "l"(src))
#define CP_COMMIT() asm volatile("cp.async.commit_group;\n")

#define LDMX4(r0, r1, r2, r3, addr)                                         \
    asm volatile("ldmatrix.sync.aligned.m8n8.x4.shared.b16 {%0,%1,%2,%3}, [%4];" \
                 : "=r"(r0), "=r"(r1), "=r"(r2), "=r"(r3) : "r"(addr))

#define MMA16816(d, a, b0, b1)                                              \
    asm volatile(                                                           \
        "mma.sync.aligned.m16n8k16.row.col.f32.f16.f16.f32 "                \
        "{%0,%1,%2,%3}, {%4,%5,%6,%7}, {%8,%9}, {%0,%1,%2,%3};\n"           \
        : "+f"((d)[0]), "+f"((d)[1]), "+f"((d)[2]), "+f"((d)[3])            \
        : "r"((a)[0]), "r"((a)[1]), "r"((a)[2]), "r"((a)[3]),               \
          "r"(b0), "r"(b1))

// ---------------------------------------------------------------------------
// K0: x NCHW -> NHWC (fp32 + fp16)
// ---------------------------------------------------------------------------
__global__ void k_transpose_x(const float* __restrict__ x) {
    __shared__ float tile[32][33];
    int b = blockIdx.z, hw0 = blockIdx.x * 32, c0 = blockIdx.y * 32;
    int tx = threadIdx.x, ty = threadIdx.y;
#pragma unroll
    for (int i = 0; i < 4; i++) {
        int c = c0 + ty + i * 8;
        tile[ty + i * 8][tx] = x[((long)b * CIN + c) * HWSZ + hw0 + tx];
    }
    __syncthreads();
#pragma unroll
    for (int i = 0; i < 4; i++) {
        int hw = hw0 + ty + i * 8;
        float v = tile[tx][ty + i * 8];
        long idx = ((long)b * HWSZ + hw) * CIN + c0 + tx;
        g_xt[idx] = v;
        g_xh[idx] = __float2half_rn(v);
    }
}

// ---------------------------------------------------------------------------
// K0b: deform_w -> fp16 B tiles  g_wtB[kb][o][ko], k = tap*256 + c
// ---------------------------------------------------------------------------
__global__ void k_prep_w(const float* __restrict__ dw) {
    int idx = blockIdx.x * 256 + threadIdx.x;
    if (idx >= NKB * 8192) return;
    int kb = idx >> 13;
    int rem = idx & 8191;
    int o = rem >> 5, ko = rem & 31;
    int tap = kb >> 3;
    int c = (kb & 7) * 32 + ko;
    g_wtB[idx] = __float2half_rn(dw[(o * CIN + c) * KT + tap]);
}

// ---------------------------------------------------------------------------
// K1: offset conv 3x3, fp32, C-split x4 (256 CTAs), partials out.
// ---------------------------------------------------------------------------
__global__ __launch_bounds__(256) void k_offset_conv(const float* __restrict__ ow) {
    int bz    = blockIdx.z;
    int b     = bz >> 2;
    int chunk = bz & 3;
    int x0 = blockIdx.x * 16, y0 = blockIdx.y * 16;
    int tid = threadIdx.x;
    int tx = tid & 15, ty = tid >> 4;

    __shared__ float sx[8][18][18];
    __shared__ float swf[8 * 9 * 20];

    float acc[20];
#pragma unroll
    for (int i = 0; i < 20; i++) acc[i] = 0.f;

    int cbeg = chunk * 64;
    for (int c0 = cbeg; c0 < cbeg + 64; c0 += 8) {
        for (int i = tid; i < 18 * 18 * 8; i += 256) {
            int cc = i & 7, p = i >> 3;
            int xx = p % 18, yy = p / 18;
            int gy = y0 + yy - 1, gx = x0 + xx - 1;
            float v = 0.f;
            if (gy >= 0 && gy < HH && gx >= 0 && gx < WW)
                v = g_xt[((b * HWSZ) + gy * WW + gx) * CIN + c0 + cc];
            sx[cc][yy][xx] = v;
        }
        for (int i = tid; i < 8 * 9 * 20; i += 256) {
            int oc = i % 20, j = (i / 20) % 9, cc = i / 180;
            swf[i] = (oc < OCOFF) ? ow[(oc * CIN + c0 + cc) * KT + j] : 0.f;
        }
        __syncthreads();
#pragma unroll
        for (int cc = 0; cc < 8; cc++) {
            float v[9];
#pragma unroll
            for (int j = 0; j < 9; j++)
                v[j] = sx[cc][ty + j / 3][tx + j % 3];
#pragma unroll
            for (int j = 0; j < 9; j++) {
                const float4* wp = reinterpret_cast<const float4*>(&swf[(cc * 9 + j) * 20]);
#pragma unroll
                for (int q = 0; q < 5; q++) {
                    float4 w = wp[q];
                    acc[q * 4 + 0] += v[j] * w.x;
                    acc[q * 4 + 1] += v[j] * w.y;
                    acc[q * 4 + 2] += v[j] * w.z;
                    acc[q * 4 + 3] += v[j] * w.w;
                }
            }
        }
        __syncthreads();
    }
    int pix = b * HWSZ + (y0 + ty) * WW + (x0 + tx);
#pragma unroll
    for (int oc = 0; oc < OCOFF; oc++)
        g_offp[chunk][pix * OCOFF + oc] = acc[oc];
}

// ---------------------------------------------------------------------------
// K2: precompute bilinear corner indices + weights (combine partials + bias)
// ---------------------------------------------------------------------------
__global__ void k_precomp(const float* __restrict__ ob) {
    int i = blockIdx.x * 256 + threadIdx.x;
    if (i >= NPIX * KT) return;
    int tp = i % 9, pix = i / 9;
    float dy = ob[2 * tp], dx = ob[2 * tp + 1];
#pragma unroll
    for (int ch = 0; ch < 4; ch++) {
        dy += g_offp[ch][pix * OCOFF + 2 * tp];
        dx += g_offp[ch][pix * OCOFF + 2 * tp + 1];
    }
    int h = (pix >> 6) & 63, w = pix & 63;
    int ky = tp / 3, kx = tp % 3;
    float py = (float)(h - 1 + ky) + dy;
    float px = (float)(w - 1 + kx) + dx;
    float y0f = floorf(py), x0f = floorf(px);
    float ty = py - y0f, tx = px - x0f;
    int y0 = (int)y0f, x0 = (int)x0f;
    int y1 = y0 + 1, x1 = x0 + 1;
    float vy0 = (y0 >= 0 && y0 < HH) ? 1.f : 0.f;
    float vy1 = (y1 >= 0 && y1 < HH) ? 1.f : 0.f;
    float vx0 = (x0 >= 0 && x0 < WW) ? 1.f : 0.f;
    float vx1 = (x1 >= 0 && x1 < WW) ? 1.f : 0.f;
    int yc0 = min(max(y0, 0), HH - 1), yc1 = min(max(y1, 0), HH - 1);
    int xc0 = min(max(x0, 0), WW - 1), xc1 = min(max(x1, 0), WW - 1);
    g_sidx[i] = make_int4(yc0 * WW + xc0, yc0 * WW + xc1,
                          yc1 * WW + xc0, yc1 * WW + xc1);
    g_sw[i] = make_float4((1.f - ty) * (1.f - tx) * vy0 * vx0,
                          (1.f - ty) * tx * vy0 * vx1,
                          ty * (1.f - tx) * vy1 * vx0,
                          ty * tx * vy1 * vx1);
}

// ---------------------------------------------------------------------------
// K3: FUSED gather + fp16 GEMM + GN partials.
//   grid=128 (M tiles of 128 px), 512 thr, BK=32, 3-stage pipeline.
//   A gathered on the fly (per thread: 1 row, 8 channels), B via cp.async.
// ---------------------------------------------------------------------------
#define ASTRIDE 40                      // halfs per smem row (32 + 8 pad)
#define A_OFF(s)  ((s) * 10240)         // 128*40*2
#define B_OFF(s)  (30720 + (s) * 20480) // 256*40*2
#define GEMM_SMEM (30720 + 3 * 20480)   // 92160

__global__ __launch_bounds__(512, 1) void k_gemm_fused() {
    extern __shared__ __align__(16) char smem[];
    uint32_t sb = sptr(smem);

    int m0 = blockIdx.x * 128;
    int b  = blockIdx.x >> 5;
    int t = threadIdx.x, lane = t & 31, wid = t >> 5;
    int wm = wid & 3, wn = wid >> 2;
    int lrow = lane & 15, lcol = (lane >> 4) * 8;

    // gather assignment: 1 row (pixel), 8 channels
    int r  = t >> 2;
    int s8 = (t & 3) * 8;
    int pixg = m0 + r;
    const __half* xb = g_xh + (size_t)b * HWSZ * CIN;

    // B load assignment
    int brow = t >> 1, bcol = (t & 1) * 16;

    float acc[2][8][4];
#pragma unroll
    for (int i = 0; i < 2; i++)
#pragma unroll
        for (int j = 0; j < 8; j++)
#pragma unroll
            for (int q = 0; q < 4; q++) acc[i][j][q] = 0.f;

    int4   I;
    float4 Wq;
    uint4  c0v, c1v, c2v, c3v;

#define GATHER_LDG(cn)                                                        \
    do {                                                                      \
        if (((cn) & 7) == 0) {                                                \
            int tap = (cn) >> 3;                                              \
            I  = g_sidx[pixg * 9 + tap];                                      \
            Wq = g_sw[pixg * 9 + tap];                                        \
        }                                                                     \
        const __half* xc = xb + ((cn) & 7) * 32 + s8;                         \
        c0v = *(const uint4*)(xc + (size_t)I.x * CIN);                        \
        c1v = *(const uint4*)(xc + (size_t)I.y * CIN);                        \
        c2v = *(const uint4*)(xc + (size_t)I.z * CIN);                        \
        c3v = *(const uint4*)(xc + (size_t)I.w * CIN);                        \
    } while (0)

#define GATHER_STORE(stg)                                                     \
    do {                                                                      \
        const __half2* h0 = (const __half2*)&c0v;                             \
        const __half2* h1 = (const __half2*)&c1v;                             \
        const __half2* h2 = (const __half2*)&c2v;                             \
        const __half2* h3 = (const __half2*)&c3v;                             \
        __half2 outv[4];                                                      \
        _Pragma("unroll")                                                     \
        for (int j = 0; j < 4; j++) {                                         \
            float2 f0 = __half22float2(h0[j]);                                \
            float2 f1 = __half22float2(h1[j]);                                \
            float2 f2 = __half22float2(h2[j]);                                \
            float2 f3 = __half22float2(h3[j]);                                \
            float2 rr;                                                        \
            rr.x = Wq.x * f0.x + Wq.y * f1.x + Wq.z * f2.x + Wq.w * f3.x;     \
            rr.y = Wq.x * f0.y + Wq.y * f1.y + Wq.z * f2.y + Wq.w * f3.y;     \
            outv[j] = __float22half2_rn(rr);                                  \
        }                                                                     \
        *(uint4*)(smem + A_OFF(stg) + (r * ASTRIDE + s8) * 2) =               \
            *(const uint4*)outv;                                              \
    } while (0)

#define LOAD_B(stg, kb)                                                       \
    do {                                                                      \
        CP_ASYNC16(sb + B_OFF(stg) + (brow * ASTRIDE + bcol) * 2,             \
                   g_wtB + (kb) * 8192 + brow * 32 + bcol);                   \
        CP_ASYNC16(sb + B_OFF(stg) + (brow * ASTRIDE + bcol + 8) * 2,         \
                   g_wtB + (kb) * 8192 + brow * 32 + bcol + 8);               \
        CP_COMMIT();                                                          \
    } while (0)

    // prologue: stages 0,1
    GATHER_LDG(0);  GATHER_STORE(0);
    GATHER_LDG(1);  GATHER_STORE(1);
    LOAD_B(0, 0);
    LOAD_B(1, 1);

    for (int c = 0; c < NKB; c++) {
        int st = c % 3;
        if (c + 2 < NKB) GATHER_LDG(c + 2);
        if (c + 1 < NKB) {
            asm volatile("cp.async.wait_group 1;" ::: "memory");
        } else {
            asm volatile("cp.async.wait_group 0;" ::: "memory");
        }
        __syncthreads();

        uint32_t Ab = sb + A_OFF(st);
        uint32_t Bb = sb + B_OFF(st);
#pragma unroll
        for (int ks = 0; ks < 32; ks += 16) {
            int col = ks + lcol;
            uint32_t A0[4], A1[4], t0, t1, t2, t3;
            LDMX4(A0[0], A0[1], A0[2], A0[3],
                  Ab + ((wm * 32 + lrow) * ASTRIDE + col) * 2);
            LDMX4(A1[0], A1[1], A1[2], A1[3],
                  Ab + ((wm * 32 + 16 + lrow) * ASTRIDE + col) * 2);
#pragma unroll
            for (int np = 0; np < 4; np++) {
                LDMX4(t0, t1, t2, t3,
                      Bb + ((wn * 64 + np * 16 + lrow) * ASTRIDE + col) * 2);
                MMA16816(acc[0][np * 2], A0, t0, t2);
                MMA16816(acc[1][np * 2], A1, t0, t2);
                MMA16816(acc[0][np * 2 + 1], A0, t1, t3);
                MMA16816(acc[1][np * 2 + 1], A1, t1, t3);
            }
        }

        if (c + 2 < NKB) {
            int wst = (c + 2) % 3;
            GATHER_STORE(wst);
            LOAD_B(wst, c + 2);
        }
        __syncthreads();
    }
#undef GATHER_LDG
#undef GATHER_STORE
#undef LOAD_B

    // ---- write P ----
#pragma unroll
    for (int mt = 0; mt < 2; mt++) {
        int row = m0 + wm * 32 + mt * 16 + (lane >> 2);
#pragma unroll
        for (int nt = 0; nt < 8; nt++) {
            int col = wn * 64 + nt * 8 + (lane & 3) * 2;
            *(float2*)&g_P[(size_t)row * COUT + col] =
                make_float2(acc[mt][nt][0], acc[mt][nt][1]);
            *(float2*)&g_P[(size_t)(row + 8) * COUT + col] =
                make_float2(acc[mt][nt][2], acc[mt][nt][3]);
        }
    }

    // ---- GN partial sums (deterministic, no atomics) ----
    __syncthreads();                       // done with A smem region
    float* sgn = (float*)smem;             // [32 groups][4 wm][2]
#pragma unroll
    for (int nt = 0; nt < 8; nt++) {
        float s = 0.f, ss = 0.f;
#pragma unroll
        for (int mt = 0; mt < 2; mt++)
#pragma unroll
            for (int q = 0; q < 4; q++) {
                float v = acc[mt][nt][q];
                s += v;  ss += v * v;
            }
#pragma unroll
        for (int off = 16; off >= 1; off >>= 1) {
            s  += __shfl_xor_sync(0xffffffffu, s, off);
            ss += __shfl_xor_sync(0xffffffffu, ss, off);
        }
        if (lane == 0) {
            int g = wn * 8 + nt;
            sgn[(g * 4 + wm) * 2 + 0] = s;
            sgn[(g * 4 + wm) * 2 + 1] = ss;
        }
    }
    __syncthreads();
    if (t < GROUPS) {
        float s = 0.f, ss = 0.f;
#pragma unroll
        for (int w = 0; w < 4; w++) {
            s  += sgn[(t * 4 + w) * 2 + 0];
            ss += sgn[(t * 4 + w) * 2 + 1];
        }
        g_gnp[blockIdx.x * GROUPS + t] = make_float2(s, ss);
    }
}

// ---------------------------------------------------------------------------
// K4: combine GN partials -> mean / rstd
// ---------------------------------------------------------------------------
__global__ void k_stats_combine() {
    int t = threadIdx.x;                   // 128 = 4 batches x 32 groups
    int b = t >> 5, g = t & 31;
    float s = 0.f, ss = 0.f;
    for (int blk = 0; blk < 32; blk++) {
        float2 v = g_gnp[(b * 32 + blk) * GROUPS + g];
        s += v.x;  ss += v.y;
    }
    float inv = 1.f / (float)(CPG * HWSZ);
    float mean = s * inv;
    float var  = ss * inv - mean * mean;
    g_stat[t * 2]     = mean;
    g_stat[t * 2 + 1] = rsqrtf(var + 1e-5f);
}

// ---------------------------------------------------------------------------
// K5: normalize + affine + ReLU + NHWC->NCHW into d_out
// ---------------------------------------------------------------------------
__global__ void k_gn_finalize(float* __restrict__ out,
                              const float* __restrict__ gamma,
                              const float* __restrict__ beta) {
    __shared__ float tile[32][33];
    int b = blockIdx.z, hw0 = blockIdx.x * 32, o0 = blockIdx.y * 32;
    int tx = threadIdx.x, ty = threadIdx.y;

    int o = o0 + tx;
    int g = o >> 3;
    float mean = g_stat[(b * GROUPS + g) * 2];
    float rstd = g_stat[(b * GROUPS + g) * 2 + 1];
    float ga = gamma[o], be = beta[o];

#pragma unroll
    for (int i = 0; i < 4; i++) {
        int hw = hw0 + ty + i * 8;
        float v = g_P[(long)(b * HWSZ + hw) * COUT + o];
        v = (v - mean) * rstd * ga + be;
        tile[ty + i * 8][tx] = fmaxf(v, 0.f);
    }
    __syncthreads();
#pragma unroll
    for (int i = 0; i < 4; i++) {
        int oo = o0 + ty + i * 8;
        out[((long)b * COUT + oo) * HWSZ + hw0 + tx] = tile[tx][ty + i * 8];
    }
}

// ---------------------------------------------------------------------------
extern "C" void kernel_launch(void* const* d_in, const int* in_sizes, int n_in,
                              void* d_out, int out_size) {
    const float* x  = (const float*)d_in[0];
    const float* ow = (const float*)d_in[1];
    const float* ob = (const float*)d_in[2];
    const float* dw = (const float*)d_in[3];
    const float* ga = (const float*)d_in[4];
    const float* be = (const float*)d_in[5];
    float* out = (float*)d_out;

    cudaFuncSetAttribute(k_gemm_fused,
                         cudaFuncAttributeMaxDynamicSharedMemorySize, GEMM_SMEM);

    k_transpose_x<<<dim3(HWSZ / 32, CIN / 32, BATCH), dim3(32, 8)>>>(x);
    k_prep_w<<<(NKB * 8192 + 255) / 256, 256>>>(dw);
    k_offset_conv<<<dim3(WW / 16, HH / 16, BATCH * 4), 256>>>(ow);
    k_precomp<<<(NPIX * KT + 255) / 256, 256>>>(ob);
    k_gemm_fused<<<NPIX / 128, 512, GEMM_SMEM>>>();
    k_stats_combine<<<1, 128>>>();
    k_gn_finalize<<<dim3(HWSZ / 32, COUT / 32, BATCH), dim3(32, 8)>>>(out, ga, be);
}

// round 7
// speedup vs baseline: 2.3634x; 1.3300x over previous
#include <cuda_runtime.h>
#include <cuda_fp16.h>
#include <cstdint>

// ---------------------------------------------------------------------------
// DeformableBlock R7: all-fp16-tensor pipeline.
//   k_prep: x -> NHWC fp16 (flat + 66x66 zero-padded) + both weight preps.
//   k_offconv16: fixed-tap im2col conv via m16n8k16 (offsets, 256->18).
//   k_precomp: bilinear corner idx/weights.
//   k_gemm_fused: on-the-fly bilinear gather + fp16 GEMM + GN partials
//                 (single barrier per mainloop iteration).
//   k_stats_combine + k_gn_finalize.
// ---------------------------------------------------------------------------

#define BATCH 4
#define CIN   256
#define COUT  256
#define HH    64
#define WW    64
#define HWSZ  4096
#define NPIX  16384
#define KT    9
#define KDIM  2304
#define OCOFF 18
#define GROUPS 32
#define CPG   8
#define NKB   72            // K chunks of 32
#define PD    66            // padded spatial dim
#define PHW   (PD*PD)       // 4356

__device__ __align__(16) __half g_xh [NPIX * CIN];          // x NHWC fp16
__device__ __align__(16) __half g_xp [BATCH * PHW * CIN];   // padded NHWC fp16
__device__ __align__(16) __half g_wtB[NKB * 256 * 32];      // deform W tiles
__device__ __align__(16) __half g_wtO[NKB * 32 * 32];       // offset W tiles
__device__ float  g_off [NPIX * OCOFF];                     // offsets (no bias)
__device__ int4   g_sidx[NPIX * KT];
__device__ float4 g_sw  [NPIX * KT];
__device__ float  g_P   [NPIX * COUT];
__device__ float2 g_gnp [128 * GROUPS];
__device__ float  g_stat[BATCH * GROUPS * 2];

static __device__ __forceinline__ uint32_t sptr(const void* p) {
    return (uint32_t)__cvta_generic_to_shared(p);
}
#define CP_ASYNC16(dst, src) \
    asm volatile("cp.async.cg.shared.global [%0], [%1], 16;\n" :: "r"(dst), "l"(src))
#define CP_COMMIT() asm volatile("cp.async.commit_group;\n")

#define LDMX4(r0, r1, r2, r3, addr)                                         \
    asm volatile("ldmatrix.sync.aligned.m8n8.x4.shared.b16 {%0,%1,%2,%3}, [%4];" \
                 : "=r"(r0), "=r"(r1), "=r"(r2), "=r"(r3) : "r"(addr))

#define MMA16816(d, a, b0, b1)                                              \
    asm volatile(                                                           \
        "mma.sync.aligned.m16n8k16.row.col.f32.f16.f16.f32 "                \
        "{%0,%1,%2,%3}, {%4,%5,%6,%7}, {%8,%9}, {%0,%1,%2,%3};\n"           \
        : "+f"((d)[0]), "+f"((d)[1]), "+f"((d)[2]), "+f"((d)[3])            \
        : "r"((a)[0]), "r"((a)[1]), "r"((a)[2]), "r"((a)[3]),               \
          "r"(b0), "r"(b1))

// ---------------------------------------------------------------------------
// K0: unified prep.  grid (128, 10, 4), 256 threads.
//   role<8 : NCHW->NHWC fp16 transpose tile (flat + padded interior)
//   role=8 : zero the 1-px border ring of g_xp (batch = z)
//   role=9 : z=0 -> g_wtB prep ; z=1 -> g_wtO prep
// ---------------------------------------------------------------------------
__global__ __launch_bounds__(256) void k_prep(const float* __restrict__ x,
                                              const float* __restrict__ dw,
                                              const float* __restrict__ ow) {
    __shared__ float tile[32][33];
    int role = blockIdx.y;
    int b = blockIdx.z;
    int t = threadIdx.x;

    if (role < 8) {
        int hw0 = blockIdx.x * 32, c0 = role * 32;
        int tx = t & 31, ty = t >> 5;
#pragma unroll
        for (int i = 0; i < 4; i++) {
            int c = c0 + ty + i * 8;
            tile[ty + i * 8][tx] = x[((long)b * CIN + c) * HWSZ + hw0 + tx];
        }
        __syncthreads();
#pragma unroll
        for (int i = 0; i < 4; i++) {
            int hw = hw0 + ty + i * 8;
            __half v = __float2half_rn(tile[tx][ty + i * 8]);
            g_xh[((size_t)b * HWSZ + hw) * CIN + c0 + tx] = v;
            int h = hw >> 6, w = hw & 63;
            g_xp[((size_t)b * PHW + (h + 1) * PD + (w + 1)) * CIN + c0 + tx] = v;
        }
    } else if (role == 8) {
        // border ring: 260 positions x 128 uint32 words = 33280 words/batch
        uint32_t* xp32 = (uint32_t*)g_xp;
        for (int i = blockIdx.x * 256 + t; i < 260 * 128; i += 128 * 256) {
            int p = i >> 7, word = i & 127;
            int y, xx;
            if (p < 66)       { y = 0;        xx = p; }
            else if (p < 132) { y = 65;       xx = p - 66; }
            else if (p < 196) { y = p - 131;  xx = 0; }
            else              { y = p - 195;  xx = 65; }
            xp32[((size_t)b * PHW + y * PD + xx) * 128 + word] = 0u;
        }
    } else {
        if (b == 0) {
            for (int i = blockIdx.x * 256 + t; i < NKB * 8192; i += 128 * 256) {
                int kb = i >> 13, rem = i & 8191;
                int o = rem >> 5, ko = rem & 31;
                int tap = kb >> 3, c = (kb & 7) * 32 + ko;
                g_wtB[i] = __float2half_rn(dw[(o * CIN + c) * KT + tap]);
            }
        } else if (b == 1) {
            for (int i = blockIdx.x * 256 + t; i < NKB * 1024; i += 128 * 256) {
                int kb = i >> 10, rem = i & 1023;
                int oc = rem >> 5, ko = rem & 31;
                int tap = kb >> 3, c = (kb & 7) * 32 + ko;
                g_wtO[i] = (oc < OCOFF)
                    ? __float2half_rn(ow[(oc * CIN + c) * KT + tap])
                    : __half(0.f);
            }
        }
    }
}

// ---------------------------------------------------------------------------
// K1: offset conv via fp16 MMA.  grid=128, 256 thr (8 warps x 16-row tiles).
//   Fixed-tap im2col from padded x, pure cp.async, 3-stage, N=32 (18 used).
// ---------------------------------------------------------------------------
__global__ __launch_bounds__(256) void k_offconv16() {
    __shared__ __align__(16) __half sA[3][128 * 40];
    __shared__ __align__(16) __half sB[3][32 * 40];
    uint32_t sbA = sptr(sA), sbB = sptr(sB);

    int t = threadIdx.x, lane = t & 31, wid = t >> 5;
    int m0 = blockIdx.x * 128;
    int r = t >> 1, seg = (t & 1) * 16;
    int pix = m0 + r;
    int b = pix >> 12, h = (pix >> 6) & 63, w = pix & 63;
    size_t basep = (size_t)b * PHW + h * PD + w;   // + ky*PD + kx
    int brow = t >> 2, bcol = (t & 3) * 8;         // B loaders: t < 128

    float acc[4][4];
#pragma unroll
    for (int i = 0; i < 4; i++)
#pragma unroll
        for (int q = 0; q < 4; q++) acc[i][q] = 0.f;

#define OLOAD(stg, kb)                                                        \
    do {                                                                      \
        int tap = (kb) >> 3, cb = ((kb) & 7) * 32 + seg;                      \
        const __half* src =                                                   \
            g_xp + (basep + (tap / 3) * PD + (tap % 3)) * CIN + cb;           \
        CP_ASYNC16(sbA + (stg) * 10240 + (r * 40 + seg) * 2, src);            \
        CP_ASYNC16(sbA + (stg) * 10240 + (r * 40 + seg + 8) * 2, src + 8);    \
        if (t < 128)                                                          \
            CP_ASYNC16(sbB + (stg) * 2560 + (brow * 40 + bcol) * 2,           \
                       g_wtO + (kb) * 1024 + brow * 32 + bcol);               \
        CP_COMMIT();                                                          \
    } while (0)

    OLOAD(0, 0);
    OLOAD(1, 1);

    int lrow = lane & 15, lcol = (lane >> 4) * 8;
    for (int c = 0; c < NKB; c++) {
        int st = c % 3;
        if (c + 1 < NKB) {
            asm volatile("cp.async.wait_group 1;" ::: "memory");
        } else {
            asm volatile("cp.async.wait_group 0;" ::: "memory");
        }
        __syncthreads();
#pragma unroll
        for (int ks = 0; ks < 32; ks += 16) {
            int col = ks + lcol;
            uint32_t A0[4], t0, t1, t2, t3;
            LDMX4(A0[0], A0[1], A0[2], A0[3],
                  sbA + st * 10240 + ((wid * 16 + lrow) * 40 + col) * 2);
#pragma unroll
            for (int np = 0; np < 2; np++) {
                LDMX4(t0, t1, t2, t3,
                      sbB + st * 2560 + ((np * 16 + lrow) * 40 + col) * 2);
                MMA16816(acc[np * 2], A0, t0, t2);
                MMA16816(acc[np * 2 + 1], A0, t1, t3);
            }
        }
        if (c + 2 < NKB) OLOAD((c + 2) % 3, c + 2);
    }
#undef OLOAD

    int rb = m0 + wid * 16 + (lane >> 2);
#pragma unroll
    for (int nt = 0; nt < 3; nt++) {
        int col = nt * 8 + (lane & 3) * 2;
        if (col < OCOFF) {
            g_off[rb * OCOFF + col] = acc[nt][0];
            g_off[(rb + 8) * OCOFF + col] = acc[nt][2];
        }
        if (col + 1 < OCOFF) {
            g_off[rb * OCOFF + col + 1] = acc[nt][1];
            g_off[(rb + 8) * OCOFF + col + 1] = acc[nt][3];
        }
    }
}

// ---------------------------------------------------------------------------
// K2: precompute bilinear corner indices + weights (adds bias)
// ---------------------------------------------------------------------------
__global__ void k_precomp(const float* __restrict__ ob) {
    int i = blockIdx.x * 256 + threadIdx.x;
    if (i >= NPIX * KT) return;
    int tp = i % 9, pix = i / 9;
    float dy = ob[2 * tp]     + g_off[pix * OCOFF + 2 * tp];
    float dx = ob[2 * tp + 1] + g_off[pix * OCOFF + 2 * tp + 1];
    int h = (pix >> 6) & 63, w = pix & 63;
    int ky = tp / 3, kx = tp % 3;
    float py = (float)(h - 1 + ky) + dy;
    float px = (float)(w - 1 + kx) + dx;
    float y0f = floorf(py), x0f = floorf(px);
    float ty = py - y0f, tx = px - x0f;
    int y0 = (int)y0f, x0 = (int)x0f;
    int y1 = y0 + 1, x1 = x0 + 1;
    float vy0 = (y0 >= 0 && y0 < HH) ? 1.f : 0.f;
    float vy1 = (y1 >= 0 && y1 < HH) ? 1.f : 0.f;
    float vx0 = (x0 >= 0 && x0 < WW) ? 1.f : 0.f;
    float vx1 = (x1 >= 0 && x1 < WW) ? 1.f : 0.f;
    int yc0 = min(max(y0, 0), HH - 1), yc1 = min(max(y1, 0), HH - 1);
    int xc0 = min(max(x0, 0), WW - 1), xc1 = min(max(x1, 0), WW - 1);
    g_sidx[i] = make_int4(yc0 * WW + xc0, yc0 * WW + xc1,
                          yc1 * WW + xc0, yc1 * WW + xc1);
    g_sw[i] = make_float4((1.f - ty) * (1.f - tx) * vy0 * vx0,
                          (1.f - ty) * tx * vy0 * vx1,
                          ty * (1.f - tx) * vy1 * vx0,
                          ty * tx * vy1 * vx1);
}

// ---------------------------------------------------------------------------
// K3: FUSED gather + fp16 GEMM + GN partials (one barrier per iteration).
// ---------------------------------------------------------------------------
#define ASTRIDE 40
#define A_OFF(s)  ((s) * 10240)
#define B_OFF(s)  (30720 + (s) * 20480)
#define GEMM_SMEM (30720 + 3 * 20480)

__global__ __launch_bounds__(512, 1) void k_gemm_fused() {
    extern __shared__ __align__(16) char smem[];
    uint32_t sb = sptr(smem);

    int m0 = blockIdx.x * 128;
    int b  = blockIdx.x >> 5;
    int t = threadIdx.x, lane = t & 31, wid = t >> 5;
    int wm = wid & 3, wn = wid >> 2;
    int lrow = lane & 15, lcol = (lane >> 4) * 8;

    int r  = t >> 2;
    int s8 = (t & 3) * 8;
    int pixg = m0 + r;
    const __half* xb = g_xh + (size_t)b * HWSZ * CIN;

    int brow = t >> 1, bcol = (t & 1) * 16;

    float acc[2][8][4];
#pragma unroll
    for (int i = 0; i < 2; i++)
#pragma unroll
        for (int j = 0; j < 8; j++)
#pragma unroll
            for (int q = 0; q < 4; q++) acc[i][j][q] = 0.f;

    int4   I;
    float4 Wq;
    uint4  c0v, c1v, c2v, c3v;

#define GATHER_LDG(cn)                                                        \
    do {                                                                      \
        if (((cn) & 7) == 0) {                                                \
            int tap = (cn) >> 3;                                              \
            I  = g_sidx[pixg * 9 + tap];                                      \
            Wq = g_sw[pixg * 9 + tap];                                        \
        }                                                                     \
        const __half* xc = xb + ((cn) & 7) * 32 + s8;                         \
        c0v = *(const uint4*)(xc + (size_t)I.x * CIN);                        \
        c1v = *(const uint4*)(xc + (size_t)I.y * CIN);                        \
        c2v = *(const uint4*)(xc + (size_t)I.z * CIN);                        \
        c3v = *(const uint4*)(xc + (size_t)I.w * CIN);                        \
    } while (0)

#define GATHER_STORE(stg)                                                     \
    do {                                                                      \
        const __half2* h0 = (const __half2*)&c0v;                             \
        const __half2* h1 = (const __half2*)&c1v;                             \
        const __half2* h2 = (const __half2*)&c2v;                             \
        const __half2* h3 = (const __half2*)&c3v;                             \
        __half2 outv[4];                                                      \
        _Pragma("unroll")                                                     \
        for (int j = 0; j < 4; j++) {                                         \
            float2 f0 = __half22float2(h0[j]);                                \
            float2 f1 = __half22float2(h1[j]);                                \
            float2 f2 = __half22float2(h2[j]);                                \
            float2 f3 = __half22float2(h3[j]);                                \
            float2 rr;                                                        \
            rr.x = Wq.x * f0.x + Wq.y * f1.x + Wq.z * f2.x + Wq.w * f3.x;     \
            rr.y = Wq.x * f0.y + Wq.y * f1.y + Wq.z * f2.y + Wq.w * f3.y;     \
            outv[j] = __float22half2_rn(rr);                                  \
        }                                                                     \
        *(uint4*)(smem + A_OFF(stg) + (r * ASTRIDE + s8) * 2) =               \
            *(const uint4*)outv;                                              \
    } while (0)

#define LOAD_B(stg, kb)                                                       \
    do {                                                                      \
        CP_ASYNC16(sb + B_OFF(stg) + (brow * ASTRIDE + bcol) * 2,             \
                   g_wtB + (kb) * 8192 + brow * 32 + bcol);                   \
        CP_ASYNC16(sb + B_OFF(stg) + (brow * ASTRIDE + bcol + 8) * 2,         \
                   g_wtB + (kb) * 8192 + brow * 32 + bcol + 8);               \
        CP_COMMIT();                                                          \
    } while (0)

    GATHER_LDG(0);  GATHER_STORE(0);
    GATHER_LDG(1);  GATHER_STORE(1);
    LOAD_B(0, 0);
    LOAD_B(1, 1);

    for (int c = 0; c < NKB; c++) {
        int st = c % 3;
        if (c + 2 < NKB) GATHER_LDG(c + 2);
        if (c + 1 < NKB) {
            asm volatile("cp.async.wait_group 1;" ::: "memory");
        } else {
            asm volatile("cp.async.wait_group 0;" ::: "memory");
        }
        __syncthreads();

        uint32_t Ab = sb + A_OFF(st);
        uint32_t Bb = sb + B_OFF(st);
#pragma unroll
        for (int ks = 0; ks < 32; ks += 16) {
            int col = ks + lcol;
            uint32_t A0[4], A1[4], t0, t1, t2, t3;
            LDMX4(A0[0], A0[1], A0[2], A0[3],
                  Ab + ((wm * 32 + lrow) * ASTRIDE + col) * 2);
            LDMX4(A1[0], A1[1], A1[2], A1[3],
                  Ab + ((wm * 32 + 16 + lrow) * ASTRIDE + col) * 2);
#pragma unroll
            for (int np = 0; np < 4; np++) {
                LDMX4(t0, t1, t2, t3,
                      Bb + ((wn * 64 + np * 16 + lrow) * ASTRIDE + col) * 2);
                MMA16816(acc[0][np * 2], A0, t0, t2);
                MMA16816(acc[1][np * 2], A1, t0, t2);
                MMA16816(acc[0][np * 2 + 1], A0, t1, t3);
                MMA16816(acc[1][np * 2 + 1], A1, t1, t3);
            }
        }

        if (c + 2 < NKB) {
            int wst = (c + 2) % 3;
            GATHER_STORE(wst);
            LOAD_B(wst, c + 2);
        }
    }
#undef GATHER_LDG
#undef GATHER_STORE
#undef LOAD_B

    // ---- write P ----
#pragma unroll
    for (int mt = 0; mt < 2; mt++) {
        int row = m0 + wm * 32 + mt * 16 + (lane >> 2);
#pragma unroll
        for (int nt = 0; nt < 8; nt++) {
            int col = wn * 64 + nt * 8 + (lane & 3) * 2;
            *(float2*)&g_P[(size_t)row * COUT + col] =
                make_float2(acc[mt][nt][0], acc[mt][nt][1]);
            *(float2*)&g_P[(size_t)(row + 8) * COUT + col] =
                make_float2(acc[mt][nt][2], acc[mt][nt][3]);
        }
    }

    // ---- GN partial sums ----
    __syncthreads();
    float* sgn = (float*)smem;
#pragma unroll
    for (int nt = 0; nt < 8; nt++) {
        float s = 0.f, ss = 0.f;
#pragma unroll
        for (int mt = 0; mt < 2; mt++)
#pragma unroll
            for (int q = 0; q < 4; q++) {
                float v = acc[mt][nt][q];
                s += v;  ss += v * v;
            }
#pragma unroll
        for (int off = 16; off >= 1; off >>= 1) {
            s  += __shfl_xor_sync(0xffffffffu, s, off);
            ss += __shfl_xor_sync(0xffffffffu, ss, off);
        }
        if (lane == 0) {
            int g = wn * 8 + nt;
            sgn[(g * 4 + wm) * 2 + 0] = s;
            sgn[(g * 4 + wm) * 2 + 1] = ss;
        }
    }
    __syncthreads();
    if (t < GROUPS) {
        float s = 0.f, ss = 0.f;
#pragma unroll
        for (int w = 0; w < 4; w++) {
            s  += sgn[(t * 4 + w) * 2 + 0];
            ss += sgn[(t * 4 + w) * 2 + 1];
        }
        g_gnp[blockIdx.x * GROUPS + t] = make_float2(s, ss);
    }
}

// ---------------------------------------------------------------------------
// K4: combine GN partials -> mean / rstd
// ---------------------------------------------------------------------------
__global__ void k_stats_combine() {
    int t = threadIdx.x;
    int b = t >> 5, g = t & 31;
    float s = 0.f, ss = 0.f;
    for (int blk = 0; blk < 32; blk++) {
        float2 v = g_gnp[(b * 32 + blk) * GROUPS + g];
        s += v.x;  ss += v.y;
    }
    float inv = 1.f / (float)(CPG * HWSZ);
    float mean = s * inv;
    float var  = ss * inv - mean * mean;
    g_stat[t * 2]     = mean;
    g_stat[t * 2 + 1] = rsqrtf(var + 1e-5f);
}

// ---------------------------------------------------------------------------
// K5: normalize + affine + ReLU + NHWC->NCHW into d_out
// ---------------------------------------------------------------------------
__global__ void k_gn_finalize(float* __restrict__ out,
                              const float* __restrict__ gamma,
                              const float* __restrict__ beta) {
    __shared__ float tile[32][33];
    int b = blockIdx.z, hw0 = blockIdx.x * 32, o0 = blockIdx.y * 32;
    int tx = threadIdx.x, ty = threadIdx.y;

    int o = o0 + tx;
    int g = o >> 3;
    float mean = g_stat[(b * GROUPS + g) * 2];
    float rstd = g_stat[(b * GROUPS + g) * 2 + 1];
    float ga = gamma[o], be = beta[o];

#pragma unroll
    for (int i = 0; i < 4; i++) {
        int hw = hw0 + ty + i * 8;
        float v = g_P[(long)(b * HWSZ + hw) * COUT + o];
        v = (v - mean) * rstd * ga + be;
        tile[ty + i * 8][tx] = fmaxf(v, 0.f);
    }
    __syncthreads();
#pragma unroll
    for (int i = 0; i < 4; i++) {
        int oo = o0 + ty + i * 8;
        out[((long)b * COUT + oo) * HWSZ + hw0 + tx] = tile[tx][ty + i * 8];
    }
}

// ---------------------------------------------------------------------------
extern "C" void kernel_launch(void* const* d_in, const int* in_sizes, int n_in,
                              void* d_out, int out_size) {
    const float* x  = (const float*)d_in[0];
    const float* ow = (const float*)d_in[1];
    const float* ob = (const float*)d_in[2];
    const float* dw = (const float*)d_in[3];
    const float* ga = (const float*)d_in[4];
    const float* be = (const float*)d_in[5];
    float* out = (float*)d_out;

    cudaFuncSetAttribute(k_gemm_fused,
                         cudaFuncAttributeMaxDynamicSharedMemorySize, GEMM_SMEM);

    k_prep<<<dim3(128, 10, 4), 256>>>(x, dw, ow);
    k_offconv16<<<128, 256>>>();
    k_precomp<<<(NPIX * KT + 255) / 256, 256>>>(ob);
    k_gemm_fused<<<NPIX / 128, 512, GEMM_SMEM>>>();
    k_stats_combine<<<1, 128>>>();
    k_gn_finalize<<<dim3(HWSZ / 32, COUT / 32, BATCH), dim3(32, 8)>>>(out, ga, be);
}